// round 5
// baseline (speedup 1.0000x reference)
#include <cuda_runtime.h>
#include <math.h>
#include <stdint.h>

// GRU: inputs[64,512,1024], h0[1,64,1024], weight_ih[3072,1024], weight_hh[3072,1024],
//      bias_ih[3072], bias_hh[3072]
// out = concat(outputs[64,512,1024], hn[1,64,1024])

#define BATCH 64
#define SEQ   512
#define IDIM  1024
#define HID   1024
#define G3    3072

#define NBLK  128        // persistent blocks
#define UPB   8          // hidden units per block
#define WPAD  1028       // weight smem row stride
#define HPAD  68         // h smem row stride
#define PPAD  25         // partials smem row stride
#define NCH   16         // 64-wide K chunks

// Scratch (device globals; no runtime allocation).
__device__ float g_xproj[(size_t)BATCH * SEQ * G3];   // exact fp32 x_proj
__device__ float g_in_r[(size_t)BATCH * SEQ * IDIM];  // tf32-rounded inputs
__device__ float g_wih_r[(size_t)G3 * IDIM];          // tf32-rounded W_ih
__device__ float g_whh_r[(size_t)G3 * IDIM];          // tf32-rounded W_hh
__device__ float g_h[4][(size_t)BATCH * HID];         // tf32-rounded h ring (4 deep)
__device__ int   g_flags[NCH];                        // per-unit-group progress counters

// ---------------------------------------------------------------------------
// helpers
// ---------------------------------------------------------------------------
__device__ __forceinline__ float tf32r(float x) {
    uint32_t o;
    asm("cvt.rna.tf32.f32 %0, %1;" : "=r"(o) : "f"(x));
    return __uint_as_float(o);
}
__device__ __forceinline__ uint32_t smem_u32(const void* p) {
    uint32_t a;
    asm("{ .reg .u64 t; cvta.to.shared.u64 t, %1; cvt.u32.u64 %0, t; }" : "=r"(a) : "l"(p));
    return a;
}
__device__ __forceinline__ void cpa16(uint32_t dst, const void* src) {
    asm volatile("cp.async.ca.shared.global [%0], [%1], 16;" :: "r"(dst), "l"(src));
}
__device__ __forceinline__ void cpa16_cg(uint32_t dst, const void* src) {
    asm volatile("cp.async.cg.shared.global [%0], [%1], 16;" :: "r"(dst), "l"(src));
}
__device__ __forceinline__ void cpa_commit() { asm volatile("cp.async.commit_group;"); }
__device__ __forceinline__ void cpa_wait0()  { asm volatile("cp.async.wait_group 0;"); }
__device__ __forceinline__ void cpa_wait1()  { asm volatile("cp.async.wait_group 1;"); }
__device__ __forceinline__ void cpa_wait2()  { asm volatile("cp.async.wait_group 2;"); }

__device__ __forceinline__ void mma8(float* c, const uint32_t* a, uint32_t b0, uint32_t b1) {
    asm volatile(
        "mma.sync.aligned.m16n8k8.row.col.f32.tf32.tf32.f32 "
        "{%0,%1,%2,%3}, {%4,%5,%6,%7}, {%8,%9}, {%0,%1,%2,%3};"
        : "+f"(c[0]), "+f"(c[1]), "+f"(c[2]), "+f"(c[3])
        : "r"(a[0]), "r"(a[1]), "r"(a[2]), "r"(a[3]), "r"(b0), "r"(b1));
}
__device__ __forceinline__ float sigmoidf_(float x) { return 1.f / (1.f + __expf(-x)); }

// Spin on a produced-counter (acquire).
__device__ __forceinline__ void wait_flag(const int* f, int target) {
    int v;
    asm volatile("ld.acquire.gpu.b32 %0, [%1];" : "=r"(v) : "l"(f));
    while (v < target) {
        asm volatile("ld.acquire.gpu.b32 %0, [%1];" : "=r"(v) : "l"(f));
    }
}

__global__ void init_flags_kernel() {
    if (threadIdx.x < NCH) g_flags[threadIdx.x] = 0;
}

// ---------------------------------------------------------------------------
// tf32 RNA rounding pre-pass
// ---------------------------------------------------------------------------
__global__ void round_kernel(const float4* __restrict__ src, float4* __restrict__ dst, int n4)
{
    int i = blockIdx.x * 256 + threadIdx.x;
    if (i < n4) {
        float4 v = src[i];
        v.x = tf32r(v.x); v.y = tf32r(v.y); v.z = tf32r(v.z); v.w = tf32r(v.w);
        dst[i] = v;
    }
}

// ---------------------------------------------------------------------------
// x_proj GEMM (tf32 mma): C[32768,3072] = A @ W^T + bias
// BM=128 BN=128 BK=16, 4-stage cp.async, 128 threads, 64x64 warp tiles.
// ---------------------------------------------------------------------------
#define XBK   16
#define XPAD  20
#define XROWS 256

__global__ __launch_bounds__(128, 2)
void xproj_v2(const float* __restrict__ A,
              const float* __restrict__ W,
              const float* __restrict__ bias)
{
    extern __shared__ float sm[];            // [4][256][20]
    const uint32_t smb = smem_u32(sm);

    const int bm = blockIdx.y, bn = blockIdx.x;
    const int tid = threadIdx.x;
    const int w = tid >> 5, lane = tid & 31;
    const int g = lane >> 2, q = lane & 3;
    const int wm = (w & 1) * 64;
    const int wn = (w >> 1) * 64;

    const float* Abase = A + (size_t)bm * 128 * IDIM;
    const float* Wbase = W + (size_t)bn * 128 * IDIM;

    float acc[4][8][4];
    #pragma unroll
    for (int i = 0; i < 4; i++)
        #pragma unroll
        for (int j = 0; j < 8; j++)
            #pragma unroll
            for (int k = 0; k < 4; k++) acc[i][j][k] = 0.f;

    auto load_stage = [&](int s) {
        int buf = s & 3;
        int k0 = s * XBK;
        #pragma unroll
        for (int i = 0; i < 8; i++) {
            int idx = tid + i * 128;
            int row = idx >> 2;
            int c   = idx & 3;
            const float* src = (row < 128)
                ? (Abase + (size_t)row * IDIM + k0 + c * 4)
                : (Wbase + (size_t)(row - 128) * IDIM + k0 + c * 4);
            cpa16(smb + (((buf * XROWS + row) * XPAD + c * 4) << 2), src);
        }
    };

    load_stage(0); cpa_commit();
    load_stage(1); cpa_commit();
    load_stage(2); cpa_commit();
    cpa_wait2();
    __syncthreads();

    for (int kc = 0; kc < 64; kc++) {
        if (kc + 3 < 64) { load_stage(kc + 3); cpa_commit(); }

        const float* S = sm + (size_t)(kc & 3) * XROWS * XPAD;
        #pragma unroll
        for (int ks = 0; ks < 2; ks++) {
            uint32_t a[4][4];
            #pragma unroll
            for (int mt = 0; mt < 4; mt++) {
                int r = wm + mt * 16;
                a[mt][0] = __float_as_uint(S[(r + g) * XPAD + ks * 8 + q]);
                a[mt][1] = __float_as_uint(S[(r + g + 8) * XPAD + ks * 8 + q]);
                a[mt][2] = __float_as_uint(S[(r + g) * XPAD + ks * 8 + q + 4]);
                a[mt][3] = __float_as_uint(S[(r + g + 8) * XPAD + ks * 8 + q + 4]);
            }
            uint32_t b0[8], b1[8];
            #pragma unroll
            for (int nt = 0; nt < 8; nt++) {
                int c = 128 + wn + nt * 8 + g;
                b0[nt] = __float_as_uint(S[c * XPAD + ks * 8 + q]);
                b1[nt] = __float_as_uint(S[c * XPAD + ks * 8 + q + 4]);
            }
            #pragma unroll
            for (int mt = 0; mt < 4; mt++)
                #pragma unroll
                for (int nt = 0; nt < 8; nt++)
                    mma8(acc[mt][nt], a[mt], b0[nt], b1[nt]);
        }

        if (kc + 1 < 64) {
            if (kc <= 60) cpa_wait2();
            else if (kc == 61) cpa_wait1();
            else cpa_wait0();
            __syncthreads();
        }
    }

    #pragma unroll
    for (int mt = 0; mt < 4; mt++) {
        #pragma unroll
        for (int nt = 0; nt < 8; nt++) {
            int row = bm * 128 + wm + mt * 16 + g;
            int col = bn * 128 + wn + nt * 8 + 2 * q;
            float b0 = bias[col], b1 = bias[col + 1];
            *(float2*)(g_xproj + (size_t)row * G3 + col) =
                make_float2(acc[mt][nt][0] + b0, acc[mt][nt][1] + b1);
            *(float2*)(g_xproj + (size_t)(row + 8) * G3 + col) =
                make_float2(acc[mt][nt][2] + b0, acc[mt][nt][3] + b1);
        }
    }
}

// ---------------------------------------------------------------------------
// Persistent dataflow GRU recurrence: 128 blocks x 128 threads.
// Block owns units j0 = bid*8 (24 GEMM cols). No global barrier: per-chunk
// produced-flags (g_flags[group] = 8 * steps_completed by that group's blocks).
// Warps K-split within each 64-wide chunk; partials reduced in smem.
// ---------------------------------------------------------------------------
__global__ __launch_bounds__(128, 1)
void gru_dataflow(const float* __restrict__ Whh_r,
                  const float* __restrict__ bhh,
                  const float* __restrict__ h0,
                  float* __restrict__ out)
{
    extern __shared__ float sm[];
    float* Ws = sm;                       // [24][WPAD]
    float* Hs = sm + 24 * WPAD;           // ring [3][64][HPAD]  (union with part)
    float* Pt = Hs;                       // partials [4][64][PPAD] (after chunks done)
    const uint32_t wsb = smem_u32(Ws);
    const uint32_t hsb = smem_u32(Hs);

    const int tid = threadIdx.x;
    const int w = tid >> 5, lane = tid & 31;
    const int g = lane >> 2, q = lane & 3;
    const int j0 = blockIdx.x * UPB;
    const int grp = blockIdx.x >> 3;      // this block's unit-group (0..15)

    // ---- resident weights: 24 rows x 1024 ----
    for (int i = tid; i < 24 * 256; i += 128) {
        int r = i >> 8, cq = i & 255;
        int gate = r >> 3, u = r & 7;
        cpa16(wsb + ((r * WPAD + cq * 4) << 2),
              Whh_r + (size_t)(gate * HID + j0 + u) * HID + cq * 4);
    }
    cpa_commit();
    cpa_wait0();
    __syncthreads();

    // ---- per-thread epilogue ownership: batch b, units j0+uh..j0+uh+3 ----
    const int b  = tid >> 1;
    const int uh = (tid & 1) * 4;
    float4 hp4 = *(const float4*)(h0 + (size_t)b * HID + j0 + uh);   // exact h
    float4 br4 = *(const float4*)(bhh + j0 + uh);
    float4 bz4 = *(const float4*)(bhh + HID + j0 + uh);
    float4 bn4 = *(const float4*)(bhh + 2 * HID + j0 + uh);
    float hp[4] = { hp4.x, hp4.y, hp4.z, hp4.w };
    const float brr[4] = { br4.x, br4.y, br4.z, br4.w };
    const float bzz[4] = { bz4.x, bz4.y, bz4.z, bz4.w };
    const float bnn[4] = { bn4.x, bn4.y, bn4.z, bn4.w };

    float* ghb = &g_h[0][0];

    for (int t = 0; t < SEQ; t++) {
        const float* hread = ghb + (size_t)(t & 3) * BATCH * HID;
        float* hwrite      = ghb + (size_t)((t + 1) & 3) * BATCH * HID;
        const int target = 8 * t;

        // prefetch x_proj gate values (consumed in epilogue)
        const float* xrow = g_xproj + ((size_t)b * SEQ + t) * G3 + j0 + uh;
        float4 xg0 = *(const float4*)(xrow);
        float4 xg1 = *(const float4*)(xrow + HID);
        float4 xg2 = *(const float4*)(xrow + 2 * HID);

        auto load_chunk = [&](int kc) {
            int stage = kc % 3;
            const float* src0 = hread + kc * 64;
            #pragma unroll
            for (int i = 0; i < 8; i++) {
                int idx = tid + i * 128;
                int bb = idx >> 4, cq = idx & 15;
                cpa16_cg(hsb + (((stage * 64 + bb) * HPAD + cq * 4) << 2),
                         src0 + (size_t)bb * HID + cq * 4);
            }
            cpa_commit();
        };

        wait_flag(&g_flags[0], target); load_chunk(0);
        wait_flag(&g_flags[1], target); load_chunk(1);

        float acc[4][3][4];
        #pragma unroll
        for (int i = 0; i < 4; i++)
            #pragma unroll
            for (int j = 0; j < 3; j++)
                #pragma unroll
                for (int k = 0; k < 4; k++) acc[i][j][k] = 0.f;

        for (int kc = 0; kc < NCH; kc++) {
            if (kc + 2 < NCH) {
                wait_flag(&g_flags[kc + 2], target);
                load_chunk(kc + 2);
            }
            if (kc + 2 < NCH)      cpa_wait2();
            else if (kc + 1 < NCH) cpa_wait1();
            else                   cpa_wait0();
            __syncthreads();

            const float* S = Hs + (size_t)(kc % 3) * 64 * HPAD;
            const int kbase = kc * 64 + w * 16;
            #pragma unroll
            for (int s = 0; s < 2; s++) {
                const int kl = w * 16 + s * 8;
                uint32_t a[4][4];
                #pragma unroll
                for (int mt = 0; mt < 4; mt++) {
                    a[mt][0] = __float_as_uint(S[(mt * 16 + g) * HPAD + kl + q]);
                    a[mt][1] = __float_as_uint(S[(mt * 16 + g + 8) * HPAD + kl + q]);
                    a[mt][2] = __float_as_uint(S[(mt * 16 + g) * HPAD + kl + q + 4]);
                    a[mt][3] = __float_as_uint(S[(mt * 16 + g + 8) * HPAD + kl + q + 4]);
                }
                #pragma unroll
                for (int nt = 0; nt < 3; nt++) {
                    uint32_t b0 = __float_as_uint(Ws[(nt * 8 + g) * WPAD + kbase + s * 8 + q]);
                    uint32_t b1 = __float_as_uint(Ws[(nt * 8 + g) * WPAD + kbase + s * 8 + q + 4]);
                    #pragma unroll
                    for (int mt = 0; mt < 4; mt++)
                        mma8(acc[mt][nt], a[mt], b0, b1);
                }
            }
            __syncthreads();
        }

        // ---- write per-warp partials (reuse h ring smem) ----
        #pragma unroll
        for (int mt = 0; mt < 4; mt++) {
            #pragma unroll
            for (int nt = 0; nt < 3; nt++) {
                int r = mt * 16 + g, c = nt * 8 + 2 * q;
                Pt[(w * 64 + r) * PPAD + c]     = acc[mt][nt][0];
                Pt[(w * 64 + r) * PPAD + c + 1] = acc[mt][nt][1];
                Pt[(w * 64 + r + 8) * PPAD + c]     = acc[mt][nt][2];
                Pt[(w * 64 + r + 8) * PPAD + c + 1] = acc[mt][nt][3];
            }
        }
        __syncthreads();

        // ---- reduce + gate + update ----
        float hx[4], hr[4];
        #pragma unroll
        for (int u = 0; u < 4; u++) {
            int col_r = 0 * 8 + uh + u;
            int col_z = 1 * 8 + uh + u;
            int col_n = 2 * 8 + uh + u;
            float sr = 0.f, sz = 0.f, sn = 0.f;
            #pragma unroll
            for (int w2 = 0; w2 < 4; w2++) {
                const float* Pb = Pt + (w2 * 64 + b) * PPAD;
                sr += Pb[col_r]; sz += Pb[col_z]; sn += Pb[col_n];
            }
            float xr = (&xg0.x)[u], xz = (&xg1.x)[u], xn = (&xg2.x)[u];
            float rr = sigmoidf_(xr + sr + brr[u]);
            float zz = sigmoidf_(xz + sz + bzz[u]);
            float nn = tanhf(xn + rr * (sn + bnn[u]));
            hx[u] = (1.f - zz) * nn + zz * hp[u];
            hp[u] = hx[u];
            hr[u] = tf32r(hx[u]);
        }
        *(float4*)(out + ((size_t)b * SEQ + t) * HID + j0 + uh) =
            make_float4(hx[0], hx[1], hx[2], hx[3]);
        *(float4*)(hwrite + (size_t)b * HID + j0 + uh) =
            make_float4(hr[0], hr[1], hr[2], hr[3]);

        // ---- publish: this group's slice of h_{t+1} is ready ----
        __threadfence();
        __syncthreads();                 // also protects Pt/Hs union reuse next step
        if (tid == 0) atomicAdd(&g_flags[grp], 1);
    }
}

// Gather h_{SEQ-1} into the contiguous hn region.
__global__ void hn_kernel(float* __restrict__ out)
{
    int i = blockIdx.x * 256 + threadIdx.x;
    int bb = i >> 10;
    int jj = i & 1023;
    out[(size_t)BATCH * SEQ * HID + i] =
        out[((size_t)bb * SEQ + (SEQ - 1)) * HID + jj];
}

// ---------------------------------------------------------------------------
extern "C" void kernel_launch(void* const* d_in, const int* in_sizes, int n_in,
                              void* d_out, int out_size)
{
    const float* inputs = (const float*)d_in[0];
    const float* h0     = (const float*)d_in[1];
    const float* wih    = (const float*)d_in[2];
    const float* whh    = (const float*)d_in[3];
    const float* bih    = (const float*)d_in[4];
    const float* bhh    = (const float*)d_in[5];
    float* out = (float*)d_out;

    const int XP_SMEM = 4 * XROWS * XPAD * 4;                        // 81920
    const int GP_SMEM = (24 * WPAD + 3 * 64 * HPAD) * 4;             // 150912
    static bool attr_done = false;
    if (!attr_done) {
        cudaFuncSetAttribute(xproj_v2, cudaFuncAttributeMaxDynamicSharedMemorySize, XP_SMEM);
        cudaFuncSetAttribute(gru_dataflow, cudaFuncAttributeMaxDynamicSharedMemorySize, GP_SMEM);
        attr_done = true;
    }

    float* in_r;  cudaGetSymbolAddress((void**)&in_r,  g_in_r);
    float* wih_r; cudaGetSymbolAddress((void**)&wih_r, g_wih_r);
    float* whh_r; cudaGetSymbolAddress((void**)&whh_r, g_whh_r);
    float* hbuf;  cudaGetSymbolAddress((void**)&hbuf,  g_h);

    // Phase -1: reset dataflow flags (required on every graph replay).
    init_flags_kernel<<<1, 32>>>();

    // Phase 0: RNA-round mma operands.
    int n4 = BATCH * SEQ * IDIM / 4;
    round_kernel<<<(n4 + 255) / 256, 256>>>((const float4*)inputs, (float4*)in_r, n4);
    n4 = G3 * IDIM / 4;
    round_kernel<<<(n4 + 255) / 256, 256>>>((const float4*)wih, (float4*)wih_r, n4);
    round_kernel<<<(n4 + 255) / 256, 256>>>((const float4*)whh, (float4*)whh_r, n4);
    n4 = BATCH * HID / 4;
    round_kernel<<<(n4 + 255) / 256, 256>>>((const float4*)h0, (float4*)hbuf, n4);

    // Phase 1: x_proj
    dim3 grid_x(G3 / 128, (BATCH * SEQ) / 128);
    xproj_v2<<<grid_x, 128, XP_SMEM>>>(in_r, wih_r, bih);

    // Phase 2: dataflow recurrence (all 512 steps, no global barrier)
    gru_dataflow<<<NBLK, 128, GP_SMEM>>>(whh_r, bhh, h0, out);

    // Phase 3: hn
    hn_kernel<<<(BATCH * HID) / 256, 256>>>(out);
}